// round 1
// baseline (speedup 1.0000x reference)
#include <cuda_runtime.h>
#include <math.h>

#define TT 512
#define BB 64
#define II 1024
#define HH 1024
#define G4 4096

// Scratch (allowed: __device__ globals, no runtime allocation).
static __device__ float g_gx[(size_t)TT * BB * G4];   // 512 MB: gx = X @ Wx^T + bx
static __device__ float g_c[BB * HH];                 // running cell state

// ---------------------------------------------------------------------------
// Kernel 1: gx[m, n] = sum_k X[m,k] * Wx[n,k] + bx[n]
//   X : [TT*BB, II] row-major (K contiguous)
//   Wx: [G4, II]    row-major (K contiguous)  -> "NT" layout, smem-staged
// Tile 128x128, 256 threads, 8x8 micro-tile, k-chunk 8.
// ---------------------------------------------------------------------------
__global__ __launch_bounds__(256) void gx_gemm_kernel(
    const float* __restrict__ X, const float* __restrict__ Wx,
    const float* __restrict__ bx)
{
    __shared__ float As[8][128];
    __shared__ float Bs[8][128];

    const int m0 = blockIdx.y << 7;
    const int n0 = blockIdx.x << 7;
    const int tid = threadIdx.x;
    const int tm = tid >> 4;         // 0..15
    const int tn = tid & 15;         // 0..15

    const int lr = tid >> 1;         // 0..127 (staging row)
    const int lq = (tid & 1) << 2;   // 0 or 4 (staging k offset)

    const float* Ap = X  + (size_t)(m0 + lr) * II + lq;
    const float* Bp = Wx + (size_t)(n0 + lr) * II + lq;

    float acc[8][8];
#pragma unroll
    for (int i = 0; i < 8; i++)
#pragma unroll
        for (int j = 0; j < 8; j++) acc[i][j] = 0.f;

    for (int k0 = 0; k0 < II; k0 += 8) {
        float4 av = *(const float4*)(Ap + k0);
        float4 bv = *(const float4*)(Bp + k0);
        __syncthreads();
        As[lq + 0][lr] = av.x; As[lq + 1][lr] = av.y;
        As[lq + 2][lr] = av.z; As[lq + 3][lr] = av.w;
        Bs[lq + 0][lr] = bv.x; Bs[lq + 1][lr] = bv.y;
        Bs[lq + 2][lr] = bv.z; Bs[lq + 3][lr] = bv.w;
        __syncthreads();
#pragma unroll
        for (int kk = 0; kk < 8; kk++) {
            float af[8], bf[8];
            *(float4*)(af)     = *(const float4*)(&As[kk][tm * 8]);
            *(float4*)(af + 4) = *(const float4*)(&As[kk][tm * 8 + 4]);
            *(float4*)(bf)     = *(const float4*)(&Bs[kk][tn * 8]);
            *(float4*)(bf + 4) = *(const float4*)(&Bs[kk][tn * 8 + 4]);
#pragma unroll
            for (int i = 0; i < 8; i++)
#pragma unroll
                for (int j = 0; j < 8; j++)
                    acc[i][j] = fmaf(af[i], bf[j], acc[i][j]);
        }
    }

#pragma unroll
    for (int i = 0; i < 8; i++) {
        float* crow = g_gx + (size_t)(m0 + tm * 8 + i) * G4 + n0 + tn * 8;
#pragma unroll
        for (int j = 0; j < 8; j++)
            crow[j] = acc[i][j] + bx[n0 + tn * 8 + j];
    }
}

// ---------------------------------------------------------------------------
// Kernel 2 (one launch per timestep):
//   g[b, r] = sum_k h_prev[b,k] * Wh[row(r), k]   (64 x 32 tile per CTA)
//   then the fused LSTM cell update for this CTA's 8 hidden units.
// grid = 128 CTAs (CTA ct owns hidden units [ct*8, ct*8+8)), 128 threads.
// Local gate row r (0..31): global row = (r>>3)*HH + u0 + (r&7)  (gate-major)
// h_t is written straight into d_out[t] so step t+1 reads it from there.
// ---------------------------------------------------------------------------
__global__ __launch_bounds__(128) void lstm_step_kernel(
    const float* __restrict__ h0, const float* __restrict__ c0,
    const float* __restrict__ Wh, const float* __restrict__ bh,
    float* __restrict__ out_base,
    float* __restrict__ hfin, float* __restrict__ cfin,
    int t, int last_full)
{
    __shared__ float Hs[16][64];   // h chunk, transposed [k][b]
    __shared__ float Ws[16][32];   // W chunk, transposed [k][r]
    __shared__ float Gs[64][33];   // gate pre-activations [b][r] (+pad)

    const int u0 = blockIdx.x << 3;
    const int tid = threadIdx.x;
    const int tb = tid & 15;       // b-group (4 batches each)
    const int tr = tid >> 4;       // r-group (4 rows each)

    const float* hprev = (t == 0) ? h0 : (out_base + (size_t)(t - 1) * BB * HH);
    const float* cinp  = (t == 0) ? c0 : g_c;
    float* hout = out_base + (size_t)t * BB * HH;
    const float* gx_t = g_gx + (size_t)t * BB * G4;

    // staging indices
    const int hb0 = tid >> 2;                 // 0..31
    const int hb1 = hb0 + 32;                 // 32..63
    const int hq  = (tid & 3) << 2;           // 0,4,8,12
    const int wr  = tid >> 2;                 // 0..31
    const int wq  = (tid & 3) << 2;
    const int wrow = ((wr >> 3) * HH) + u0 + (wr & 7);   // global Wh row

    const float* Hp0 = hprev + (size_t)hb0 * HH + hq;
    const float* Hp1 = hprev + (size_t)hb1 * HH + hq;
    const float* Wp  = Wh + (size_t)wrow * HH + wq;

    float acc[4][4];
#pragma unroll
    for (int i = 0; i < 4; i++)
#pragma unroll
        for (int j = 0; j < 4; j++) acc[i][j] = 0.f;

    for (int k0 = 0; k0 < HH; k0 += 16) {
        float4 hv0 = *(const float4*)(Hp0 + k0);
        float4 hv1 = *(const float4*)(Hp1 + k0);
        float4 wv  = *(const float4*)(Wp + k0);
        __syncthreads();
        Hs[hq + 0][hb0] = hv0.x; Hs[hq + 1][hb0] = hv0.y;
        Hs[hq + 2][hb0] = hv0.z; Hs[hq + 3][hb0] = hv0.w;
        Hs[hq + 0][hb1] = hv1.x; Hs[hq + 1][hb1] = hv1.y;
        Hs[hq + 2][hb1] = hv1.z; Hs[hq + 3][hb1] = hv1.w;
        Ws[wq + 0][wr] = wv.x; Ws[wq + 1][wr] = wv.y;
        Ws[wq + 2][wr] = wv.z; Ws[wq + 3][wr] = wv.w;
        __syncthreads();
#pragma unroll
        for (int kk = 0; kk < 16; kk++) {
            float hf[4], wf[4];
            *(float4*)hf = *(const float4*)(&Hs[kk][tb * 4]);
            *(float4*)wf = *(const float4*)(&Ws[kk][tr * 4]);
#pragma unroll
            for (int i = 0; i < 4; i++)
#pragma unroll
                for (int j = 0; j < 4; j++)
                    acc[i][j] = fmaf(hf[i], wf[j], acc[i][j]);
        }
    }

    __syncthreads();
#pragma unroll
    for (int i = 0; i < 4; i++)
#pragma unroll
        for (int j = 0; j < 4; j++)
            Gs[tb * 4 + i][tr * 4 + j] = acc[i][j];
    __syncthreads();

    // LSTM cell update: 512 (b, u) pairs, 4 per thread.
#pragma unroll
    for (int rep = 0; rep < 4; rep++) {
        int p = tid + rep * 128;
        int b = p >> 3;
        int u = p & 7;
        int col = u0 + u;
        const float* gxrow = gx_t + (size_t)b * G4;
        float xi = Gs[b][u]      + gxrow[col]          + bh[col];
        float xf = Gs[b][8 + u]  + gxrow[HH + col]     + bh[HH + col];
        float xo = Gs[b][16 + u] + gxrow[2 * HH + col] + bh[2 * HH + col];
        float xn = Gs[b][24 + u] + gxrow[3 * HH + col] + bh[3 * HH + col];

        float ig = 1.f / (1.f + __expf(-xi));
        float fg = 1.f / (1.f + __expf(-xf));
        float og = 1.f / (1.f + __expf(-xo));
        float ng = tanhf(xn);

        float cprev = cinp[(size_t)b * HH + col];
        float cnew  = fg * cprev + ig * ng;
        float hnew  = og * tanhf(cnew);

        g_c[(size_t)b * HH + col]  = cnew;
        hout[(size_t)b * HH + col] = hnew;
        if (last_full) {
            hfin[(size_t)b * HH + col] = hnew;
            cfin[(size_t)b * HH + col] = cnew;
        }
    }
}

// ---------------------------------------------------------------------------
// Launch: gx GEMM, then 512 sequential step kernels (default stream order).
// ---------------------------------------------------------------------------
extern "C" void kernel_launch(void* const* d_in, const int* in_sizes, int n_in,
                              void* d_out, int out_size)
{
    const float* input_ = (const float*)d_in[0];
    const float* h0     = (const float*)d_in[1];
    const float* c0     = (const float*)d_in[2];
    const float* Wx     = (const float*)d_in[3];
    const float* Wh     = (const float*)d_in[4];
    const float* bx     = (const float*)d_in[5];
    const float* bh     = (const float*)d_in[6];
    float* out = (float*)d_out;

    (void)in_sizes; (void)n_in;

    // gx = X @ Wx^T + bx for all timesteps at once
    dim3 ggrid(G4 / 128, (TT * BB) / 128);
    gx_gemm_kernel<<<ggrid, 256>>>(input_, Wx, bx);

    // Output layout: [outputs (T*B*H)] [h_f (B*H)] [c_f (B*H)] — only write the
    // tail if the harness actually allocated it.
    long long need = (long long)TT * BB * HH + 2LL * BB * HH;
    int full = (out_size >= need) ? 1 : 0;
    float* hfin = out + (size_t)TT * BB * HH;
    float* cfin = hfin + (size_t)BB * HH;

    for (int t = 0; t < TT; t++) {
        int lastf = (t == TT - 1) ? full : 0;
        lstm_step_kernel<<<128, 128>>>(h0, c0, Wh, bh, out, hfin, cfin, t, lastf);
    }
}